// round 17
// baseline (speedup 1.0000x reference)
#include <cuda_runtime.h>

#define G_   1024
#define N_   65536
#define D_   128
#define E_   400000

// Scratch (device globals — no allocations allowed)
__device__ __align__(16) float g_A[G_ * 128];        // assembled A (64 scorer | 64 type cols)
__device__ __align__(16) float g_Apart[4 * G_ * 128]; // K-slice partials
__device__ __align__(16) float g_C[N_ * 128];        // node @ W1[384:512] + A[n2g[node]]

// packed f32x2 helpers (full-rate FMA pipe; scalar 3-reg FFMA is half-rate)
__device__ __forceinline__ unsigned long long fma2(unsigned long long a, unsigned long long b,
                                                   unsigned long long c) {
    unsigned long long d;
    asm("fma.rn.f32x2 %0, %1, %2, %3;" : "=l"(d) : "l"(a), "l"(b), "l"(c));
    return d;
}
__device__ __forceinline__ unsigned long long pack2(float lo, float hi) {
    unsigned long long d;
    asm("mov.b64 %0, {%1, %2};" : "=l"(d) : "f"(lo), "f"(hi));
    return d;
}
__device__ __forceinline__ void unpack2(unsigned long long v, float& lo, float& hi) {
    asm("mov.b64 {%0, %1}, %2;" : "=f"(lo), "=f"(hi) : "l"(v));
}

// ---------------------------------------------------------------------------
// kA v4: K-split GEMM partials. grid (256, 4). (R16, measured good)
// ---------------------------------------------------------------------------
__global__ void kA(const float* __restrict__ imr, const float* __restrict__ pgr,
                   const float* __restrict__ nodes, const int* __restrict__ focus,
                   const float* __restrict__ sW1, const float* __restrict__ tW1) {
    __shared__ float xs[4][96];
    __shared__ int foc[4];
    int j = threadIdx.x;
    int g0 = blockIdx.x * 4;
    int s = blockIdx.y;
    int kbase = s * 96;
    if (j < 4) foc[j] = focus[g0 + j];
    __syncthreads();
    for (int idx = j; idx < 4 * 96; idx += 128) {
        int r = idx / 96, kk = idx - r * 96;
        int kg = kbase + kk;
        float v;
        if (kg < 128)      v = imr[(size_t)(g0 + r) * 128 + kg];
        else if (kg < 256) v = pgr[(size_t)(g0 + r) * 128 + (kg - 128)];
        else               v = nodes[(size_t)foc[r] * 128 + (kg - 256)];
        xs[r][kk] = v;
    }
    __syncthreads();
    bool isS = (j < 64);
    const float* W = (isS ? (sW1 + j) : (tW1 + (j - 64))) + (size_t)kbase * 64;
    float a0 = 0.f, a1 = 0.f, a2 = 0.f, a3 = 0.f;
#pragma unroll 8
    for (int k = 0; k < 96; k++) {
        float w = W[k * 64];
        a0 = fmaf(xs[0][k], w, a0);
        a1 = fmaf(xs[1][k], w, a1);
        a2 = fmaf(xs[2][k], w, a2);
        a3 = fmaf(xs[3][k], w, a3);
    }
    float* o = g_Apart + (size_t)s * (G_ * 128) + (size_t)g0 * 128 + j;
    o[0] = a0; o[128] = a1; o[256] = a2; o[384] = a3;
}

// ---------------------------------------------------------------------------
// kR: g_A = bias + sum of 4 K-slice partials.
// ---------------------------------------------------------------------------
__global__ void kR(const float* __restrict__ sb1, const float* __restrict__ tb1) {
    int i = blockIdx.x * 256 + threadIdx.x;
    int j = i & 127;
    float b = (j < 64) ? sb1[j] : tb1[j - 64];
    g_A[i] = b + g_Apart[i] + g_Apart[G_ * 128 + i]
               + g_Apart[2 * G_ * 128 + i] + g_Apart[3 * G_ * 128 + i];
}

// ---------------------------------------------------------------------------
// kB: blocks 0-511 GEMM (measured-best); blocks 512-515 stop logits (hidden).
// ---------------------------------------------------------------------------
__global__ __launch_bounds__(512, 2) void kB(const float* __restrict__ nodes,
                                             const float* __restrict__ sW1,
                                             const float* __restrict__ tW1,
                                             const int* __restrict__ n2g,
                                             const float* __restrict__ no_more,
                                             const float* __restrict__ sW2,
                                             const float* __restrict__ sb2,
                                             float* __restrict__ out) {
    __shared__ float xs[32][132];   // [k][r] transposed, padded
    __shared__ float sw[32][128];   // [k][j] combined cols
    int tid = threadIdx.x;

    if (blockIdx.x >= 512) {
        __shared__ float part[4][64];
        __shared__ float cst[64];
        int b = blockIdx.x - 512;
        if (tid < 256) {
            int j = tid & 63, s = tid >> 6;
            float sum = 0.f;
#pragma unroll 3
            for (int k = s * 33; k < s * 33 + 33; k++)
                sum += no_more[k] * sW1[(384 + k) * 64 + j];
            part[s][j] = sum;
        }
        __syncthreads();
        if (tid < 64)
            cst[tid] = part[0][tid] + part[1][tid] + part[2][tid] + part[3][tid];
        __syncthreads();
        int lane = tid & 31, wid = tid >> 5;
        float ws0 = sW2[lane], ws1 = sW2[32 + lane];
        float c0v = cst[lane], c1v = cst[32 + lane];
        float sb = sb2[0];
        for (int i = 0; i < 16; i++) {
            int g = b * 256 + i * 16 + wid;
            float a0 = g_A[(size_t)g * 128 + lane];
            float a1 = g_A[(size_t)g * 128 + 32 + lane];
            float v = fmaxf(a0 + c0v, 0.f) * ws0 + fmaxf(a1 + c1v, 0.f) * ws1;
#pragma unroll
            for (int o = 16; o >= 1; o >>= 1) v += __shfl_xor_sync(0xffffffffu, v, o);
            if (lane == 0) out[E_ + g] = v + sb;
        }
        return;
    }

    int tx = tid & 31, ty = tid >> 5;
    int c0 = tx * 4, r0 = ty * 8;
    int row0 = blockIdx.x * 128;

    unsigned long long acc[4][4];
#pragma unroll
    for (int i = 0; i < 4; i++)
#pragma unroll
        for (int j = 0; j < 4; j++) acc[i][j] = 0ull;

    for (int kc = 0; kc < 128; kc += 32) {
        for (int i = tid; i < 32 * 128; i += 512) {
            int k = i >> 7, j = i & 127;
            sw[k][j] = (j < 64) ? sW1[(384 + kc + k) * 64 + j]
                                : tW1[(384 + kc + k) * 64 + (j - 64)];
        }
        for (int f = tid; f < 1024; f += 512) {
            int r = f >> 3, kq = (f & 7) << 2;
            float4 v = *(const float4*)(nodes + (size_t)(row0 + r) * 128 + kc + kq);
            xs[kq + 0][r] = v.x; xs[kq + 1][r] = v.y;
            xs[kq + 2][r] = v.z; xs[kq + 3][r] = v.w;
        }
        __syncthreads();
#pragma unroll 8
        for (int k = 0; k < 32; k++) {
            const unsigned long long* xp = (const unsigned long long*)&xs[k][r0];
            unsigned long long x0 = xp[0], x1 = xp[1], x2 = xp[2], x3 = xp[3];
            float4 w = *(const float4*)&sw[k][c0];
            unsigned long long w0 = pack2(w.x, w.x), w1 = pack2(w.y, w.y);
            unsigned long long w2 = pack2(w.z, w.z), w3 = pack2(w.w, w.w);
            acc[0][0] = fma2(x0, w0, acc[0][0]); acc[0][1] = fma2(x0, w1, acc[0][1]);
            acc[0][2] = fma2(x0, w2, acc[0][2]); acc[0][3] = fma2(x0, w3, acc[0][3]);
            acc[1][0] = fma2(x1, w0, acc[1][0]); acc[1][1] = fma2(x1, w1, acc[1][1]);
            acc[1][2] = fma2(x1, w2, acc[1][2]); acc[1][3] = fma2(x1, w3, acc[1][3]);
            acc[2][0] = fma2(x2, w0, acc[2][0]); acc[2][1] = fma2(x2, w1, acc[2][1]);
            acc[2][2] = fma2(x2, w2, acc[2][2]); acc[2][3] = fma2(x2, w3, acc[2][3]);
            acc[3][0] = fma2(x3, w0, acc[3][0]); acc[3][1] = fma2(x3, w1, acc[3][1]);
            acc[3][2] = fma2(x3, w2, acc[3][2]); acc[3][3] = fma2(x3, w3, acc[3][3]);
        }
        __syncthreads();
    }
#pragma unroll
    for (int i = 0; i < 4; i++) {
        float lo[4], hi[4];
#pragma unroll
        for (int j = 0; j < 4; j++) unpack2(acc[i][j], lo[j], hi[j]);
        int rowA = row0 + r0 + 2 * i;
        int gA = n2g[rowA], gB = n2g[rowA + 1];
        float4 a0 = *(const float4*)(g_A + (size_t)gA * 128 + c0);
        float4 b0 = *(const float4*)(g_A + (size_t)gB * 128 + c0);
        *(float4*)(g_C + (size_t)rowA * 128 + c0) =
            make_float4(lo[0] + a0.x, lo[1] + a0.y, lo[2] + a0.z, lo[3] + a0.w);
        *(float4*)(g_C + (size_t)(rowA + 1) * 128 + c0) =
            make_float4(hi[0] + b0.x, hi[1] + b0.y, hi[2] + b0.z, hi[3] + b0.w);
    }
}

// ---------------------------------------------------------------------------
// kE v4: register diet + 5 CTAs/SM. vs measured-best v3:
//   - w512/dist-scalar replaced by in-smem distC table (1 LDS.128/edge)
//   - f2 prefetch dropped (c2 prefetch of the dependent targets->C chain kept)
//   - __launch_bounds__(256,5) caps regs at 48 -> 40 warps/SM (62.5% occ)
//   - single-wave grid: 740 blocks
// NOTE: distC smem index uses combined col cb (= +64 for type lanes).
// ---------------------------------------------------------------------------
__global__ __launch_bounds__(256, 5) void kE(const int* __restrict__ targets,
                   const float4* __restrict__ feats4,
                   const float* __restrict__ sW1, const float* __restrict__ tW1,
                   const float* __restrict__ sW2, const float* __restrict__ sb2,
                   const float* __restrict__ tW2, const float* __restrict__ tb2,
                   const float* __restrict__ dist_table,
                   float* __restrict__ out) {
    __shared__ __align__(16) float sdc[10 * 128];   // [d][combined col] = dist*w512
    for (int i = threadIdx.x; i < 10 * 128; i += 256) {
        int dd = i >> 7, col = i & 127;
        float w = (col < 64) ? sW1[512 * 64 + col] : tW1[512 * 64 + (col - 64)];
        sdc[i] = dist_table[dd] * w;
    }
    __syncthreads();

    int lane = threadIdx.x & 31;
    bool isS = (lane < 16);
    int cbase = (lane & 15) * 4;            // col within 64-wide W1 arrays
    int cb = cbase + (isS ? 0 : 64);        // col within combined 128 (distC)
    const float* W1 = isS ? sW1 : tW1;
    float4 w513 = *(const float4*)(W1 + 513 * 64 + cbase);
    float4 w514 = *(const float4*)(W1 + 514 * 64 + cbase);
    float4 w515 = *(const float4*)(W1 + 515 * 64 + cbase);
    float4 u0, u1, u2;
    if (isS) {
        u0 = *(const float4*)(sW2 + cbase);
        u1 = make_float4(0.f, 0.f, 0.f, 0.f);
        u2 = u1;
    } else {
        u0.x = tW2[(cbase + 0) * 3]; u0.y = tW2[(cbase + 1) * 3];
        u0.z = tW2[(cbase + 2) * 3]; u0.w = tW2[(cbase + 3) * 3];
        u1.x = tW2[(cbase + 0) * 3 + 1]; u1.y = tW2[(cbase + 1) * 3 + 1];
        u1.z = tW2[(cbase + 2) * 3 + 1]; u1.w = tW2[(cbase + 3) * 3 + 1];
        u2.x = tW2[(cbase + 0) * 3 + 2]; u2.y = tW2[(cbase + 1) * 3 + 2];
        u2.z = tW2[(cbase + 2) * 3 + 2]; u2.w = tW2[(cbase + 3) * 3 + 2];
    }
    float sb2v = sb2[0];
    float tb0 = tb2[0], tb1v = tb2[1], tb2v = tb2[2];
    const float4* C4 = (const float4*)g_C;
    float* outT = out + (E_ + G_);

    int gw = (blockIdx.x * blockDim.x + threadIdx.x) >> 5;
    int nw = (gridDim.x * blockDim.x) >> 5;

    int e = gw;
    float4 c;
    if (e < E_) {
        int t = targets[e];
        c = C4[(size_t)t * 32 + lane];
    }
    while (e < E_) {
        int e2 = e + nw;
        float4 c2;
        if (e2 < E_) {
            int t2 = targets[e2];
            c2 = C4[(size_t)t2 * 32 + lane];
        }
        float4 f = feats4[e];
        int d = (int)fminf(f.x, 9.0f);
        float4 dc = *(const float4*)&sdc[d * 128 + cb];
        float hx = fmaxf(fmaf(f.y, w513.x, fmaf(f.z, w514.x, fmaf(f.w, w515.x, c.x + dc.x))), 0.f);
        float hy = fmaxf(fmaf(f.y, w513.y, fmaf(f.z, w514.y, fmaf(f.w, w515.y, c.y + dc.y))), 0.f);
        float hz = fmaxf(fmaf(f.y, w513.z, fmaf(f.z, w514.z, fmaf(f.w, w515.z, c.z + dc.z))), 0.f);
        float hw = fmaxf(fmaf(f.y, w513.w, fmaf(f.z, w514.w, fmaf(f.w, w515.w, c.w + dc.w))), 0.f);
        float v0 = fmaf(hx, u0.x, fmaf(hy, u0.y, fmaf(hz, u0.z, hw * u0.w)));
        float v1 = fmaf(hx, u1.x, fmaf(hy, u1.y, fmaf(hz, u1.z, hw * u1.w)));
        float v2 = fmaf(hx, u2.x, fmaf(hy, u2.y, fmaf(hz, u2.z, hw * u2.w)));
        float p = isS ? v0 : v1;
        float q = __shfl_xor_sync(0xffffffffu, v0, 16);
        q = isS ? q : v2;
#pragma unroll
        for (int o = 1; o <= 8; o <<= 1) {
            p += __shfl_xor_sync(0xffffffffu, p, o);
            q += __shfl_xor_sync(0xffffffffu, q, o);
        }
        if (lane == 0) {
            out[e] = p + sb2v;          // scorer logit
            outT[3 * e] = q + tb0;      // type logit 0
        }
        if (lane == 16) {
            outT[3 * e + 1] = p + tb1v; // type logit 1
            outT[3 * e + 2] = q + tb2v; // type logit 2
        }
        e = e2; c = c2;
    }
}

// ---------------------------------------------------------------------------
extern "C" void kernel_launch(void* const* d_in, const int* in_sizes, int n_in,
                              void* d_out, int out_size) {
    const float* imr     = (const float*)d_in[0];
    const float* pgr     = (const float*)d_in[1];
    const float* nodes   = (const float*)d_in[2];
    const int*   focus   = (const int*)d_in[3];
    const int*   n2g     = (const int*)d_in[4];
    const int*   targets = (const int*)d_in[5];
    const float* feats   = (const float*)d_in[6];
    int p = 7;
    if (p < n_in && in_sizes[p] == 1) p++;  // skip num_graphs_in_batch scalar if present
    const float* dist_table = (const float*)d_in[p++];  // [10]
    const float* no_more    = (const float*)d_in[p++];  // [132]
    const float* sW1 = (const float*)d_in[p++];         // [516,64]
    const float* sb1 = (const float*)d_in[p++];         // [64]
    const float* sW2 = (const float*)d_in[p++];         // [64]
    const float* sb2 = (const float*)d_in[p++];         // [1]
    const float* tW1 = (const float*)d_in[p++];         // [516,64]
    const float* tb1 = (const float*)d_in[p++];         // [64]
    const float* tW2 = (const float*)d_in[p++];         // [64,3]
    const float* tb2 = (const float*)d_in[p++];         // [3]
    float* out = (float*)d_out;

    kA<<<dim3(G_ / 4, 4), 128>>>(imr, pgr, nodes, focus, sW1, tW1);
    kR<<<G_ * 128 / 256, 256>>>(sb1, tb1);
    kB<<<N_ / 128 + 4, 512>>>(nodes, sW1, tW1, n2g, no_more, sW2, sb2, out);
    kE<<<740, 256>>>(targets, (const float4*)feats, sW1, tW1, sW2, sb2, tW2, tb2,
                     dist_table, out);
}